// round 7
// baseline (speedup 1.0000x reference)
#include <cuda_runtime.h>
#include <cuda_bf16.h>
#include <mma.h>
#include <cstdint>

using namespace nvcuda;

#define MAX_NODES 100000
#define MAX_EDGES 1600000
#define D 128

// ---------------------------------------------------------------------------
// Scratch (__device__ globals: allocation-free rule)
// A_cat = [mean_agg | x] as bf16 hi/lo, layout [node][k], k = 0..255
// ---------------------------------------------------------------------------
__device__ __align__(16) unsigned short g_Ahi[(size_t)MAX_NODES * 256];
__device__ __align__(16) unsigned short g_Alo[(size_t)MAX_NODES * 256];
__device__ int g_count[MAX_NODES];
__device__ int g_rowptr[MAX_NODES + 1];
__device__ int g_cursor[MAX_NODES];
__device__ int g_csr_src[MAX_EDGES];
__device__ int g_is64;
// W_cat = [W_l ; W_r] as [128 out-cols][256 k] bf16 hi/lo
__device__ __align__(16) unsigned short g_Whi[128 * 256];
__device__ __align__(16) unsigned short g_Wlo[128 * 256];

#define SCAN_T 256
#define SCAN_B 128
#define SCAN_PER 4   // 128*256*4 = 131072 >= 100001
__device__ int g_blocksum[SCAN_B];

// ---------------------------------------------------------------------------
// Phase -1: detect edge_index dtype (int64 vs int32)
// ---------------------------------------------------------------------------
__global__ void detect_kernel(const int* __restrict__ ei32) {
    if (threadIdx.x == 0 && blockIdx.x == 0) {
        int nz = 0;
#pragma unroll 1
        for (int i = 0; i < 64; i++) nz |= ei32[2 * i + 1];
        g_is64 = (nz == 0) ? 1 : 0;
    }
}

__global__ void init_kernel(int N) {
    int i = blockIdx.x * blockDim.x + threadIdx.x;
    if (i < N) g_count[i] = 0;
}

// Phase 1: degree histogram (reads edge_index directly)
__global__ void hist_kernel(const int* __restrict__ ei32, int E) {
    int e = blockIdx.x * blockDim.x + threadIdx.x;
    if (e >= E) return;
    int d = g_is64 ? ei32[2 * (E + e)] : ei32[E + e];
    atomicAdd(&g_count[d], 1);
}

// Phase 0b: preconvert W_cat to bf16 hi/lo, layout [o][k], k=0..255
__global__ void wconv_kernel(const float* __restrict__ Wl, const float* __restrict__ Wr) {
    int t = blockIdx.x * blockDim.x + threadIdx.x;
    if (t >= 128 * 256) return;
    int o = t >> 8, k = t & 255;
    float w = (k < 128) ? Wl[o * 128 + k] : Wr[o * 128 + (k - 128)];
    __nv_bfloat16 hi = __float2bfloat16(w);
    float rem = w - __bfloat162float(hi);
    g_Whi[t] = __bfloat16_as_ushort(hi);
    g_Wlo[t] = __bfloat16_as_ushort(__float2bfloat16(rem));
}

// ---------------------------------------------------------------------------
// Phase 2: exclusive scan of g_count -> g_rowptr (3 kernels)
// ---------------------------------------------------------------------------
__global__ __launch_bounds__(SCAN_T) void scan1_kernel(int N) {
    __shared__ int sh[SCAN_T];
    int t = threadIdx.x, b = blockIdx.x;
    int base = (b * SCAN_T + t) * SCAN_PER;
    int v[SCAN_PER];
    int s = 0;
#pragma unroll
    for (int i = 0; i < SCAN_PER; i++) {
        v[i] = (base + i < N) ? g_count[base + i] : 0;
        s += v[i];
    }
    sh[t] = s;
    __syncthreads();
    for (int off = 1; off < SCAN_T; off <<= 1) {
        int xv = (t >= off) ? sh[t - off] : 0;
        __syncthreads();
        sh[t] += xv;
        __syncthreads();
    }
    int run = sh[t] - s;
#pragma unroll
    for (int i = 0; i < SCAN_PER; i++) {
        if (base + i < N) g_rowptr[base + i] = run;
        run += v[i];
    }
    if (t == SCAN_T - 1) g_blocksum[b] = sh[t];
}

__global__ __launch_bounds__(SCAN_B) void scan2_kernel() {
    __shared__ int sh[SCAN_B];
    int t = threadIdx.x;
    int orig = g_blocksum[t];
    sh[t] = orig;
    __syncthreads();
    for (int off = 1; off < SCAN_B; off <<= 1) {
        int xv = (t >= off) ? sh[t - off] : 0;
        __syncthreads();
        sh[t] += xv;
        __syncthreads();
    }
    g_blocksum[t] = sh[t] - orig;
}

__global__ __launch_bounds__(SCAN_T) void scan3_kernel(int N, int E) {
    int t = threadIdx.x, b = blockIdx.x;
    int off = g_blocksum[b];
    int base = (b * SCAN_T + t) * SCAN_PER;
#pragma unroll
    for (int i = 0; i < SCAN_PER; i++) {
        int idx = base + i;
        if (idx < N) {
            int r = g_rowptr[idx] + off;
            g_rowptr[idx] = r;
            g_cursor[idx] = r;
        }
    }
    if (b == 0 && t == 0) g_rowptr[N] = E;
}

// Phase 3: fill CSR src lists (reads edge_index directly)
__global__ void fill_kernel(const int* __restrict__ ei32, int E) {
    int e = blockIdx.x * blockDim.x + threadIdx.x;
    if (e >= E) return;
    int s, d;
    if (g_is64) { s = ei32[2 * e]; d = ei32[2 * (E + e)]; }
    else        { s = ei32[e];     d = ei32[E + e]; }
    int pos = atomicAdd(&g_cursor[d], 1);
    g_csr_src[pos] = s;
}

// ---------------------------------------------------------------------------
// Phase 4: gather-aggregate (mean) + bf16 hi/lo conversion epilogue.
// One warp per dst node; lane owns one float4 (k = 4*lane .. 4*lane+3).
// Writes: mean -> A_cat cols 0..127;  x row -> A_cat cols 128..255.
// ---------------------------------------------------------------------------
__device__ __forceinline__ uint2 split_hi(const float4 v, uint2& lo) {
    __nv_bfloat16 a0 = __float2bfloat16(v.x), a1 = __float2bfloat16(v.y);
    __nv_bfloat16 a2 = __float2bfloat16(v.z), a3 = __float2bfloat16(v.w);
    uint2 hi;
    hi.x = (uint32_t)__bfloat16_as_ushort(a0) | ((uint32_t)__bfloat16_as_ushort(a1) << 16);
    hi.y = (uint32_t)__bfloat16_as_ushort(a2) | ((uint32_t)__bfloat16_as_ushort(a3) << 16);
    lo.x = (uint32_t)__bfloat16_as_ushort(__float2bfloat16(v.x - __bfloat162float(a0))) |
           ((uint32_t)__bfloat16_as_ushort(__float2bfloat16(v.y - __bfloat162float(a1))) << 16);
    lo.y = (uint32_t)__bfloat16_as_ushort(__float2bfloat16(v.z - __bfloat162float(a2))) |
           ((uint32_t)__bfloat16_as_ushort(__float2bfloat16(v.w - __bfloat162float(a3))) << 16);
    return hi;
}

__global__ __launch_bounds__(256) void agg_kernel(const float* __restrict__ x, int N) {
    int w = (blockIdx.x * blockDim.x + threadIdx.x) >> 5;
    int lane = threadIdx.x & 31;
    if (w >= N) return;
    int beg = g_rowptr[w];
    int end = g_rowptr[w + 1];
    const float4* xb = reinterpret_cast<const float4*>(x);
    float4 acc = make_float4(0.f, 0.f, 0.f, 0.f);
    int e = beg;
    for (; e + 3 < end; e += 4) {
        int s0 = g_csr_src[e];
        int s1 = g_csr_src[e + 1];
        int s2 = g_csr_src[e + 2];
        int s3 = g_csr_src[e + 3];
        float4 a = __ldg(xb + (size_t)s0 * 32 + lane);
        float4 b = __ldg(xb + (size_t)s1 * 32 + lane);
        float4 c = __ldg(xb + (size_t)s2 * 32 + lane);
        float4 d = __ldg(xb + (size_t)s3 * 32 + lane);
        acc.x += a.x + b.x + c.x + d.x;
        acc.y += a.y + b.y + c.y + d.y;
        acc.z += a.z + b.z + c.z + d.z;
        acc.w += a.w + b.w + c.w + d.w;
    }
    for (; e < end; e++) {
        int s = g_csr_src[e];
        float4 a = __ldg(xb + (size_t)s * 32 + lane);
        acc.x += a.x; acc.y += a.y; acc.z += a.z; acc.w += a.w;
    }
    float inv = 1.0f / fmaxf((float)(end - beg), 1.0f);
    acc.x *= inv; acc.y *= inv; acc.z *= inv; acc.w *= inv;

    // epilogue: bf16 hi/lo split of mean (cols 0..127) and x row (cols 128..255)
    uint2 lo, hi;
    hi = split_hi(acc, lo);
    size_t rb = (size_t)w * 256;
    *reinterpret_cast<uint2*>(g_Ahi + rb + lane * 4) = hi;
    *reinterpret_cast<uint2*>(g_Alo + rb + lane * 4) = lo;

    float4 xv = __ldg(xb + (size_t)w * 32 + lane);
    hi = split_hi(xv, lo);
    *reinterpret_cast<uint2*>(g_Ahi + rb + 128 + lane * 4) = hi;
    *reinterpret_cast<uint2*>(g_Alo + rb + 128 + lane * 4) = lo;
}

// ---------------------------------------------------------------------------
// Phase 5: WMMA bf16 GEMM, 3-term compensated split, pure bf16 staging.
//   out[128n x 128o] = Acat[128 x 256] * Wcat^T + bias
// CTA: 128x128, 256 threads = 8 warps, warp tile 32x64 (2x4 frags).
// K chunks of 32, smem stride 40 halves (80B rows: 16B-aligned, ldmatrix
// bank phases {0,5,2,7,4,1,6,3} conflict-free). Bias tile aliases staging
// blob (consumed into accumulators before the main loop).
// ---------------------------------------------------------------------------
#define ASTR 40

__global__ __launch_bounds__(256, 2) void gemm_wmma_kernel(
    const float* __restrict__ bl,
    float* __restrict__ out,
    int N) {
    __shared__ __align__(16) char blob[4 * 128 * ASTR * 2];  // 40960 B
    __nv_bfloat16* ahi_s = reinterpret_cast<__nv_bfloat16*>(blob);
    __nv_bfloat16* alo_s = ahi_s + 128 * ASTR;
    __nv_bfloat16* whi_s = alo_s + 128 * ASTR;
    __nv_bfloat16* wlo_s = whi_s + 128 * ASTR;
    float* bias_s = reinterpret_cast<float*>(blob);          // aliased, pre-loop only

    const int tid = threadIdx.x;
    const int wid = tid >> 5;
    const int node0 = blockIdx.x * 128;
    const int wr = (wid & 3) * 32;   // warp row offset
    const int wc = (wid >> 2) * 64;  // warp col offset

    // bias tile: 16 identical rows of bl[0..127] (in aliased region)
    {
        float bv = __ldg(bl + (tid & 127));
        int r0 = tid >> 7;
#pragma unroll
        for (int r = 0; r < 16; r += 2)
            bias_s[(r + r0) * 128 + (tid & 127)] = bv;
    }
    __syncthreads();

    wmma::fragment<wmma::accumulator, 16, 16, 16, float> acc[2][4];
#pragma unroll
    for (int i = 0; i < 2; i++)
#pragma unroll
        for (int j = 0; j < 4; j++)
            wmma::load_matrix_sync(acc[i][j], &bias_s[wc + j * 16], 128, wmma::mem_row_major);

    const int row = tid >> 1;         // 0..127 (node row AND W out-col)
    const int seg = (tid & 1) * 16;   // 16-half segment
    const int gn  = node0 + row;
    const bool va = (gn < N);
    const size_t arb = (size_t)gn * 256;

#pragma unroll 1
    for (int c = 0; c < 8; c++) {
        __syncthreads();   // acc-frag loads done / previous compute done
        // ---- stage A chunk (pure bf16 uint4 copies) ----
        {
            uint4 h0, h1, l0, l1;
            if (va) {
                const uint4* hp = reinterpret_cast<const uint4*>(g_Ahi + arb + c * 32 + seg);
                const uint4* lp = reinterpret_cast<const uint4*>(g_Alo + arb + c * 32 + seg);
                h0 = __ldg(hp); h1 = __ldg(hp + 1);
                l0 = __ldg(lp); l1 = __ldg(lp + 1);
            } else {
                h0 = h1 = l0 = l1 = make_uint4(0, 0, 0, 0);
            }
            uint4* hd = reinterpret_cast<uint4*>(&ahi_s[row * ASTR + seg]);
            uint4* ld = reinterpret_cast<uint4*>(&alo_s[row * ASTR + seg]);
            hd[0] = h0; hd[1] = h1;
            ld[0] = l0; ld[1] = l1;
        }
        // ---- stage W chunk ----
        {
            const uint4* hp = reinterpret_cast<const uint4*>(g_Whi + row * 256 + c * 32 + seg);
            const uint4* lp = reinterpret_cast<const uint4*>(g_Wlo + row * 256 + c * 32 + seg);
            uint4* hd = reinterpret_cast<uint4*>(&whi_s[row * ASTR + seg]);
            uint4* ld = reinterpret_cast<uint4*>(&wlo_s[row * ASTR + seg]);
            hd[0] = __ldg(hp); hd[1] = __ldg(hp + 1);
            ld[0] = __ldg(lp); ld[1] = __ldg(lp + 1);
        }
        __syncthreads();

        // ---- compute: 2 k-steps x (2 row frags x 4 col frags x 3 passes) ----
#pragma unroll
        for (int ks = 0; ks < 2; ks++) {
            wmma::fragment<wmma::matrix_a, 16, 16, 16, __nv_bfloat16, wmma::row_major> ah[2], al[2];
            wmma::fragment<wmma::matrix_b, 16, 16, 16, __nv_bfloat16, wmma::col_major> bh[4], blf[4];
#pragma unroll
            for (int i = 0; i < 2; i++) {
                wmma::load_matrix_sync(ah[i], &ahi_s[(wr + i * 16) * ASTR + ks * 16], ASTR);
                wmma::load_matrix_sync(al[i], &alo_s[(wr + i * 16) * ASTR + ks * 16], ASTR);
            }
#pragma unroll
            for (int j = 0; j < 4; j++) {
                wmma::load_matrix_sync(bh[j],  &whi_s[(wc + j * 16) * ASTR + ks * 16], ASTR);
                wmma::load_matrix_sync(blf[j], &wlo_s[(wc + j * 16) * ASTR + ks * 16], ASTR);
            }
#pragma unroll
            for (int i = 0; i < 2; i++)
#pragma unroll
                for (int j = 0; j < 4; j++) {
                    wmma::mma_sync(acc[i][j], ah[i], bh[j],  acc[i][j]);
                    wmma::mma_sync(acc[i][j], ah[i], blf[j], acc[i][j]);
                    wmma::mma_sync(acc[i][j], al[i], bh[j],  acc[i][j]);
                }
        }
    }

    // ---- epilogue: direct fragment stores (bias already in acc) ----
#pragma unroll
    for (int i = 0; i < 2; i++) {
        int r0 = node0 + wr + i * 16;
        if (r0 < N) {  // N % 16 == 0 -> frag fully valid
#pragma unroll
            for (int j = 0; j < 4; j++)
                wmma::store_matrix_sync(out + (size_t)r0 * D + wc + j * 16, acc[i][j], D, wmma::mem_row_major);
        }
    }
}

// ---------------------------------------------------------------------------
extern "C" void kernel_launch(void* const* d_in, const int* in_sizes, int n_in,
                              void* d_out, int out_size) {
    const float* x    = (const float*)d_in[0];
    const int*   ei32 = (const int*)d_in[1];
    const float* Wl   = (const float*)d_in[2];
    const float* bl   = (const float*)d_in[3];
    const float* Wr   = (const float*)d_in[4];
    float*       out  = (float*)d_out;

    int N = in_sizes[0] / D;       // 100000
    int E = in_sizes[1] / 2;       // 1600000

    detect_kernel<<<1, 32>>>(ei32);
    init_kernel<<<(N + 255) / 256, 256>>>(N);
    hist_kernel<<<(E + 255) / 256, 256>>>(ei32, E);
    wconv_kernel<<<(128 * 256 + 255) / 256, 256>>>(Wl, Wr);
    scan1_kernel<<<SCAN_B, SCAN_T>>>(N);
    scan2_kernel<<<1, SCAN_B>>>();
    scan3_kernel<<<SCAN_B, SCAN_T>>>(N, E);
    fill_kernel<<<(E + 255) / 256, 256>>>(ei32, E);
    agg_kernel<<<(N * 32 + 255) / 256, 256>>>(x, N);
    gemm_wmma_kernel<<<(N + 127) / 128, 256>>>(bl, out, N);
}